// round 10
// baseline (speedup 1.0000x reference)
#include <cuda_runtime.h>
#include <cuda_fp16.h>
#include <stdint.h>
#include <math.h>

#define U_CNT 30000
#define I_CNT 60000
#define G_CNT 2000
#define N_UI  90000
#define N_TOT 92000

// ---------------- device scratch (static, no allocation) ----------------
__device__ __half g_curh[N_UI * 64];
__device__ __half g_curl[N_UI * 64];
__device__ __half g_msgh[G_CNT * 64];
__device__ __half g_msgl[G_CNT * 64];
__device__ float  g_curf[N_UI * 64];
__device__ float  g_msgf[G_CNT * 64];
__device__ float  g_msgu[G_CNT * 64];
__device__ float  g_msgi[G_CNT * 64];
// [0]=cur absmax, [1]=cur binv, [2]=msg absmax, [3]=msg binv
__device__ float  g_scales[4];

// ---------------- PTX helpers ----------------
__device__ __forceinline__ uint32_t smem_u32(const void* p) {
    uint32_t a;
    asm("{ .reg .u64 t; cvta.to.shared.u64 t, %1; cvt.u32.u64 %0, t; }" : "=r"(a) : "l"(p));
    return a;
}
__device__ __forceinline__ uint32_t f16x2(float lo, float hi) {  // low=f16(lo), high=f16(hi)
    uint32_t r;
    asm("cvt.rn.f16x2.f32 %0, %1, %2;" : "=r"(r) : "f"(hi), "f"(lo));
    return r;
}
__device__ __forceinline__ void ldsm4(uint32_t* r, uint32_t addr) {
    asm volatile("ldmatrix.sync.aligned.m8n8.x4.shared.b16 {%0,%1,%2,%3}, [%4];"
                 : "=r"(r[0]), "=r"(r[1]), "=r"(r[2]), "=r"(r[3]) : "r"(addr));
}
__device__ __forceinline__ void ldsm4t(uint32_t* r, uint32_t addr) {
    asm volatile("ldmatrix.sync.aligned.m8n8.x4.trans.shared.b16 {%0,%1,%2,%3}, [%4];"
                 : "=r"(r[0]), "=r"(r[1]), "=r"(r[2]), "=r"(r[3]) : "r"(addr));
}
__device__ __forceinline__ void mma16816(float* c, const uint32_t* a, uint32_t b0, uint32_t b1) {
    asm volatile("mma.sync.aligned.m16n8k16.row.col.f32.f16.f16.f32 "
                 "{%0,%1,%2,%3}, {%4,%5,%6,%7}, {%8,%9}, {%0,%1,%2,%3};"
                 : "+f"(c[0]), "+f"(c[1]), "+f"(c[2]), "+f"(c[3])
                 : "r"(a[0]), "r"(a[1]), "r"(a[2]), "r"(a[3]), "r"(b0), "r"(b1));
}
__device__ __forceinline__ void cpasync16(uint32_t dst, const void* src, uint32_t sz) {
    asm volatile("cp.async.ca.shared.global [%0], [%1], 16, %2;"
                 :: "r"(dst), "l"(src), "r"(sz) : "memory");
}
__device__ __forceinline__ void cpasync_commit() {
    asm volatile("cp.async.commit_group;" ::: "memory");
}
__device__ __forceinline__ void cpasync_wait0() {
    asm volatile("cp.async.wait_group 0;" ::: "memory");
}
__device__ __forceinline__ void atomic_fmax(float* addr, float v) {   // v >= 0
    atomicMax((unsigned int*)addr, __float_as_uint(v));
}

// ---------------- smem layout: swizzled 128B rows ----------------
#define O_AH   0u        // A fp16 plane: 128 x 64 x 2B = 16K
#define O_BH   16384u    // B hi plane:    64 x 64 x 2B =  8K
#define O_BL   24576u    // B lo plane:                    8K
#define BUFB   32768u
#define SM_TOT 65536

// ---------------- fused GEMM:  C[M,64] = A[M,K](f32,[0,1)) @ B[K,64] ----------------
// 256 threads, 8 warps: 4 in M (32 rows) x 2 in N (32 cols). Warp tile 32x32.
// Per k-step: 6 ldsm.x4 vs 16 HMMA -> tensor-bound.
// A -> fp16 single term; B = fp16 hi/lo planes (dynamically pre-scaled).
// C = binv * (A*Bh + A*Bl), f32 accum.
template <bool ATOMIC>
__global__ void __launch_bounds__(256, 2)
gemm_mma(const float* __restrict__ A,
         const __half* __restrict__ Bh_g, const __half* __restrict__ Bl_g,
         float* __restrict__ Cacc, float* __restrict__ outAdd,
         float* __restrict__ Cout, float* __restrict__ amax,
         const float* __restrict__ binv_p,
         int M, int K, int kChunk)
{
    extern __shared__ char sm[];
    const uint32_t sb = smem_u32(sm);
    const int tid  = threadIdx.x;
    const int lane = tid & 31;
    const int wid  = tid >> 5;       // 0..7
    const int wy   = wid & 3;        // m-quadrant (32 rows)
    const int wx   = wid >> 2;       // n-half (32 cols)

    const int m0   = blockIdx.x << 7;
    const int k0   = blockIdx.y * kChunk;
    const int kEnd = min(k0 + kChunk, K);
    const int nb   = (kEnd - k0 + 63) >> 6;

    // fragment addressing (swizzled 16B units within 128B rows)
    const int li = lane >> 3, lr = lane & 7;
    const int chi = li >> 1, rsel = li & 1;
    const uint32_t ra0 = (uint32_t)((wy * 32 + rsel * 8 + lr) * 128);
    const uint32_t ra1 = ra0 + 16u * 128u;
    const uint32_t brow = (uint32_t)((rsel * 8 + lr) * 128);
    const uint32_t bc0 = brow + (uint32_t)((((wx * 4 + 0 + chi) ^ lr)) << 4);   // n-half 0
    const uint32_t bc1 = brow + (uint32_t)((((wx * 4 + 2 + chi) ^ lr)) << 4);   // n-half 1

    // A loader: row = tid>>1 (0..127), half-selector splits 16 float4 chunks into 2 waves
    const int ar = tid >> 1, ac2 = tid & 1;
    const float* Arow = A + (size_t)(m0 + ar) * K;
    const bool amok = (m0 + ar) < M;
    const uint32_t ar7 = (uint32_t)(ar & 7);

    // B loader (cp.async): kr = tid>>2 (0..63), bc16 = tid&3 -> chunks bc16, bc16+4
    const int kr = tid >> 2, bc16 = tid & 3;

    float accA[2][4][4], accB[2][4][4];
#pragma unroll
    for (int i = 0; i < 2; i++)
#pragma unroll
        for (int j = 0; j < 4; j++)
#pragma unroll
            for (int q = 0; q < 4; q++) { accA[i][j][q] = 0.f; accB[i][j][q] = 0.f; }

    auto loadA_half = [&](int h, int kb, float4* av) {
#pragma unroll
        for (int q = 0; q < 4; q++) {
            const int c = h * 8 + ac2 * 4 + q;       // float4 chunk 0..15
            const int kk = c * 4;
            float4 v = make_float4(0.f, 0.f, 0.f, 0.f);
            if (amok) {
                if (kb + kk + 3 < kEnd) v = *(const float4*)(Arow + kb + kk);
                else { float* pv = (float*)&v;
                    for (int t = 0; t < 4; t++) if (kb + kk + t < kEnd) pv[t] = Arow[kb + kk + t]; }
            }
            av[q] = v;
        }
    };
    auto storeA_half = [&](int h, uint32_t bufo, const float4* av) {
#pragma unroll
        for (int q = 0; q < 4; q++) {
            const int c = h * 8 + ac2 * 4 + q;
            const float4 v = av[q];
            const uint32_t h01 = f16x2(v.x, v.y);
            const uint32_t h23 = f16x2(v.z, v.w);
            const uint32_t off = (uint32_t)(ar * 128)
                               + ((((uint32_t)(c >> 1)) ^ ar7) << 4)
                               + ((uint32_t)(c & 1) << 3);
            *(uint2*)(sm + bufo + O_AH + off) = make_uint2(h01, h23);
        }
    };
    auto issueB = [&](uint32_t bufo, int kb) {
        const int kg = kb + kr;
        const uint32_t sz = (kg < kEnd) ? 16u : 0u;
#pragma unroll
        for (int w = 0; w < 2; w++) {
            const int cc = bc16 + 4 * w;
            const uint32_t dst = (uint32_t)(kr * 128) + ((((uint32_t)cc ^ (uint32_t)(kr & 7))) << 4);
            cpasync16(sb + bufo + O_BH + dst, Bh_g + (size_t)kg * 64 + cc * 8, sz);
            cpasync16(sb + bufo + O_BL + dst, Bl_g + (size_t)kg * 64 + cc * 8, sz);
        }
    };

    // ---- MMA for one k-step
    auto mma_step = [&](uint32_t bo, int ks) {
        uint32_t ah[8], bh[8], bl[8];
        const uint32_t asw = (uint32_t)(((ks * 2 + chi) ^ lr) << 4);
        const uint32_t ko = (uint32_t)(ks * 2048);
        ldsm4(ah,     sb + bo + O_AH + ra0 + asw);
        ldsm4(ah + 4, sb + bo + O_AH + ra1 + asw);
        ldsm4t(bh,     sb + bo + O_BH + bc0 + ko);
        ldsm4t(bh + 4, sb + bo + O_BH + bc1 + ko);
        ldsm4t(bl,     sb + bo + O_BL + bc0 + ko);
        ldsm4t(bl + 4, sb + bo + O_BL + bc1 + ko);
#pragma unroll
        for (int mt = 0; mt < 2; mt++)
#pragma unroll
            for (int nt = 0; nt < 4; nt++)
                mma16816(accA[mt][nt], ah + 4 * mt, bh[2 * nt], bh[2 * nt + 1]);
#pragma unroll
        for (int mt = 0; mt < 2; mt++)
#pragma unroll
            for (int nt = 0; nt < 4; nt++)
                mma16816(accB[mt][nt], ah + 4 * mt, bl[2 * nt], bl[2 * nt + 1]);
    };

    // ---- fill buffer 0
    {
        float4 av[4];
        loadA_half(0, k0, av);
        issueB(0u, k0);
        cpasync_commit();
        storeA_half(0, 0u, av);
        loadA_half(1, k0, av);
        storeA_half(1, 0u, av);
        cpasync_wait0();
    }
    __syncthreads();

    for (int b = 0; b < nb; b++) {
        const uint32_t bo  = (uint32_t)(b & 1) * BUFB;
        const uint32_t nbo = BUFB - bo;
        const bool more = (b + 1 < nb);
        const int kbn = k0 + ((b + 1) << 6);

        float4 av[4];
        if (more) {
            loadA_half(0, kbn, av);
            issueB(nbo, kbn);
            cpasync_commit();
        }
        mma_step(bo, 0);
        mma_step(bo, 1);
        if (more) {
            storeA_half(0, nbo, av);
            loadA_half(1, kbn, av);
        }
        mma_step(bo, 2);
        mma_step(bo, 3);
        if (more) {
            storeA_half(1, nbo, av);
            cpasync_wait0();
        }
        __syncthreads();
    }

    // ---- epilogue
    const float binv = *binv_p;
    float vmax = 0.f;
#pragma unroll
    for (int mt = 0; mt < 2; mt++) {
        const int rbase = m0 + wy * 32 + mt * 16 + (lane >> 2);
#pragma unroll
        for (int nt = 0; nt < 4; nt++) {
            const int j = wx * 32 + nt * 8 + (lane & 3) * 2;
#pragma unroll
            for (int half = 0; half < 2; half++) {
                const int r = rbase + half * 8;
                if (r < M) {
                    const int idx = r * 64 + j;
                    const float v0 = (accA[mt][nt][half * 2]     + accB[mt][nt][half * 2])     * binv;
                    const float v1 = (accA[mt][nt][half * 2 + 1] + accB[mt][nt][half * 2 + 1]) * binv;
                    if (ATOMIC) {
                        atomicAdd(&Cacc[idx], v0);
                        atomicAdd(&Cacc[idx + 1], v1);
                    } else {
                        float2 o = *(float2*)&outAdd[idx];
                        o.x += v0; o.y += v1;
                        *(float2*)&outAdd[idx] = o;
                        Cout[idx]     = v0;
                        Cout[idx + 1] = v1;
                        vmax = fmaxf(vmax, fmaxf(fabsf(v0), fabsf(v1)));
                    }
                }
            }
        }
    }
    if (!ATOMIC) {
#pragma unroll
        for (int o = 16; o > 0; o >>= 1)
            vmax = fmaxf(vmax, __shfl_xor_sync(0xFFFFFFFFu, vmax, o));
        __shared__ float wm[8];
        if (lane == 0) wm[wid] = vmax;
        __syncthreads();
        if (tid == 0) {
            float m = wm[0];
#pragma unroll
            for (int i = 1; i < 8; i++) m = fmaxf(m, wm[i]);
            atomic_fmax(amax, m);
        }
    }
}

// ---------------- conversion: fp32 tensor -> scaled fp16 hi/lo planes ----------------
__global__ void conv_plane(const float* __restrict__ X,
                           __half* __restrict__ H, __half* __restrict__ L,
                           int n, const float* __restrict__ amax_p,
                           float* __restrict__ binv_p)
{
    const float m = fmaxf(*amax_p, 1e-30f);
    int e;
    frexpf(m, &e);                              // m = f * 2^e, f in [0.5,1)
    const float s = exp2f((float)(7 - e));      // scaled max in (64,128]
    if (blockIdx.x == 0 && threadIdx.x == 0) *binv_p = exp2f((float)(e - 7));
    const int stride = gridDim.x * blockDim.x;
    for (int i = blockIdx.x * blockDim.x + threadIdx.x; i < n; i += stride) {
        const float v = X[i] * s;
        const __half h = __float2half_rn(v);
        H[i] = h;
        L[i] = __float2half_rn(v - __half2float(h));
    }
}

// ---------------- init: out = [ue;ie;ge]; curf = concat(ue,ie); absmax ----------------
__global__ void init_all(const float* __restrict__ ue, const float* __restrict__ ie,
                         const float* __restrict__ ge, float* __restrict__ out,
                         float* __restrict__ curf, float* __restrict__ amax)
{
    const int i = blockIdx.x * blockDim.x + threadIdx.x;
    const int t = N_UI * 64;
    float v = 0.f;
    if (i < t) {
        v = (i < U_CNT * 64) ? ue[i] : ie[i - U_CNT * 64];
        out[i] = v;
        curf[i] = v;
    } else if (i < t + G_CNT * 64) {
        out[i] = ge[i - t];
    }
    float a = (i < t) ? fabsf(v) : 0.f;
#pragma unroll
    for (int o = 16; o > 0; o >>= 1)
        a = fmaxf(a, __shfl_xor_sync(0xFFFFFFFFu, a, o));
    __shared__ float wm[8];
    const int lane = threadIdx.x & 31, wid = threadIdx.x >> 5;
    if (lane == 0) wm[wid] = a;
    __syncthreads();
    if (threadIdx.x == 0) {
        float m = wm[0];
#pragma unroll
        for (int q = 1; q < 8; q++) m = fmaxf(m, wm[q]);
        atomic_fmax(amax, m);
    }
}

__global__ void zero_msgs(float* __restrict__ mu, float* __restrict__ mi,
                          float* __restrict__ scales)
{
    const int i = blockIdx.x * blockDim.x + threadIdx.x;
    if (i < G_CNT * 64) { mu[i] = 0.f; mi[i] = 0.f; }
    if (i == 0) { scales[0] = 0.f; scales[2] = 0.f; }
}

// ---------------- per-group attention + MLP fusion ----------------
__global__ void __launch_bounds__(256)
group_kernel(const float* __restrict__ mu, const float* __restrict__ mi,
             const float* __restrict__ gemb,
             const float* __restrict__ qc_w1, const float* __restrict__ qc_b1,
             const float* __restrict__ qc_w2,
             const float* __restrict__ user_w, const float* __restrict__ user_b,
             const float* __restrict__ item_w, const float* __restrict__ item_b,
             float* __restrict__ msgf, float* __restrict__ out,
             float* __restrict__ amax)
{
    const int sub = threadIdx.x >> 6, j = threadIdx.x & 63;
    const int g = blockIdx.x * 4 + sub;
    __shared__ float xu[4][64], xi[4][64], ge[4][64], du[4][64], di[4][64], rA[4][64], rB[4][64];

    xu[sub][j] = mu[g * 64 + j];
    xi[sub][j] = mi[g * 64 + j];
    ge[sub][j] = gemb[g * 64 + j];
    __syncthreads();
    {
        float hu = qc_b1[j], hi = qc_b1[j];
#pragma unroll 8
        for (int k = 0; k < 64; k++) {
            const float w = qc_w1[k * 64 + j];
            hu = fmaf(xu[sub][k], w, hu);
            hi = fmaf(xi[sub][k], w, hi);
        }
        const float w2 = qc_w2[j];
        rA[sub][j] = tanhf(hu) * w2;
        rB[sub][j] = tanhf(hi) * w2;
    }
    __syncthreads();
    for (int s = 32; s > 0; s >>= 1) {
        if (j < s) { rA[sub][j] += rA[sub][j + s]; rB[sub][j] += rB[sub][j + s]; }
        __syncthreads();
    }
    const float qu = rA[sub][0], qi = rB[sub][0];
    const float mx = fmaxf(qu, qi);
    const float eu = expf(qu - mx), ei = expf(qi - mx);
    const float w0 = eu / (eu + ei), w1 = ei / (eu + ei);
    const float c = w0 * xu[sub][j] + w1 * xi[sub][j];
    du[sub][j] = xu[sub][j] - c;
    di[sub][j] = xi[sub][j] - c;
    __syncthreads();

    float u2 = user_b[j], i2 = item_b[j];
#pragma unroll 8
    for (int k = 0; k < 64; k++) {
        u2 = fmaf(du[sub][k], user_w[k * 64 + j], u2);
        i2 = fmaf(di[sub][k], item_w[k * 64 + j], i2);
    }
#pragma unroll 8
    for (int k = 0; k < 64; k++) {
        const float gv = ge[sub][k];
        u2 = fmaf(gv, user_w[(64 + k) * 64 + j], u2);
        i2 = fmaf(gv, item_w[(64 + k) * 64 + j], i2);
    }
    const float m = u2 + i2 + c;
    out[N_UI * 64 + g * 64 + j] += m;
    msgf[g * 64 + j] = m;

    float a = fabsf(m);
#pragma unroll
    for (int o = 16; o > 0; o >>= 1)
        a = fmaxf(a, __shfl_xor_sync(0xFFFFFFFFu, a, o));
    __shared__ float wm[8];
    const int lane = threadIdx.x & 31, wid = threadIdx.x >> 5;
    if (lane == 0) wm[wid] = a;
    __syncthreads();
    if (threadIdx.x == 0) {
        float mm = wm[0];
#pragma unroll
        for (int q = 1; q < 8; q++) mm = fmaxf(mm, wm[q]);
        atomic_fmax(amax, mm);
    }
}

// ---------------- launch ----------------
extern "C" void kernel_launch(void* const* d_in, const int* in_sizes, int n_in,
                              void* d_out, int out_size)
{
    const float* user_emb   = (const float*)d_in[0];
    const float* item_emb   = (const float*)d_in[1];
    const float* group_emb  = (const float*)d_in[2];
    const float* user_hyper = (const float*)d_in[3];
    const float* item_hyper = (const float*)d_in[4];
    const float* full_hyper = (const float*)d_in[5];
    int wbase = 6;
    if (n_in >= 15 && in_sizes[6] == 1 && in_sizes[7] == 1) wbase = 8;
    const float* qc_w1  = (const float*)d_in[wbase + 0];
    const float* qc_b1  = (const float*)d_in[wbase + 1];
    const float* qc_w2  = (const float*)d_in[wbase + 2];
    const float* user_w = (const float*)d_in[wbase + 3];
    const float* user_b = (const float*)d_in[wbase + 4];
    const float* item_w = (const float*)d_in[wbase + 5];
    const float* item_b = (const float*)d_in[wbase + 6];
    float* out = (float*)d_out;

    __half *ch, *cl, *mh, *ml;
    float *curf, *msgf, *mu, *mi, *scales;
    cudaGetSymbolAddress((void**)&ch, g_curh);
    cudaGetSymbolAddress((void**)&cl, g_curl);
    cudaGetSymbolAddress((void**)&mh, g_msgh);
    cudaGetSymbolAddress((void**)&ml, g_msgl);
    cudaGetSymbolAddress((void**)&curf, g_curf);
    cudaGetSymbolAddress((void**)&msgf, g_msgf);
    cudaGetSymbolAddress((void**)&mu, g_msgu);
    cudaGetSymbolAddress((void**)&mi, g_msgi);
    cudaGetSymbolAddress((void**)&scales, g_scales);

    cudaFuncSetAttribute(gemm_mma<true>,  cudaFuncAttributeMaxDynamicSharedMemorySize, SM_TOT);
    cudaFuncSetAttribute(gemm_mma<false>, cudaFuncAttributeMaxDynamicSharedMemorySize, SM_TOT);

    zero_msgs<<<(G_CNT * 64 + 255) / 256, 256>>>(mu, mi, scales);
    init_all<<<(N_TOT * 64 + 255) / 256, 256>>>(user_emb, item_emb, group_emb, out,
                                                curf, &scales[0]);
    conv_plane<<<4096, 256>>>(curf, ch, cl, N_UI * 64, &scales[0], &scales[1]);

    for (int l = 0; l < 2; l++) {
        zero_msgs<<<(G_CNT * 64 + 255) / 256, 256>>>(mu, mi, scales);

        // msg_u = user_hyper @ cur[:U]      (split-K x18, atomics)
        gemm_mma<true><<<dim3(16, 18), 256, SM_TOT>>>(
            user_hyper, ch, cl, mu, nullptr, nullptr, nullptr, &scales[1],
            G_CNT, U_CNT, 1728);
        // msg_i = item_hyper @ cur[U:]
        gemm_mma<true><<<dim3(16, 18), 256, SM_TOT>>>(
            item_hyper, ch + (size_t)U_CNT * 64, cl + (size_t)U_CNT * 64,
            mi, nullptr, nullptr, nullptr, &scales[1],
            G_CNT, I_CNT, 3392);
        // attention + MLPs -> msg fp32 + absmax ; out_he += msg
        group_kernel<<<G_CNT / 4, 256>>>(mu, mi, group_emb,
            qc_w1 + l * 64 * 64, qc_b1 + l * 64, qc_w2 + l * 64,
            user_w + l * 128 * 64, user_b + l * 64,
            item_w + l * 128 * 64, item_b + l * 64, msgf, out, &scales[2]);
        // msg planes
        conv_plane<<<512, 256>>>(msgf, mh, ml, G_CNT * 64, &scales[2], &scales[3]);
        // node_emb = full_hyper @ msg ; out += ; cur fp32 + absmax
        gemm_mma<false><<<dim3(704, 1), 256, SM_TOT>>>(
            full_hyper, mh, ml, nullptr, out, curf, &scales[0], &scales[3],
            N_UI, G_CNT, 2048);
        // cur planes for next layer
        if (l == 0)
            conv_plane<<<4096, 256>>>(curf, ch, cl, N_UI * 64, &scales[0], &scales[1]);
    }
    (void)in_sizes; (void)n_in; (void)out_size;
}

// round 11
// speedup vs baseline: 1.1373x; 1.1373x over previous
#include <cuda_runtime.h>
#include <cuda_fp16.h>
#include <stdint.h>
#include <math.h>

#define U_CNT 30000
#define I_CNT 60000
#define G_CNT 2000
#define N_UI  90000
#define N_TOT 92000

// ---------------- device scratch (static, no allocation) ----------------
__device__ __half g_curh[N_UI * 64];
__device__ __half g_curl[N_UI * 64];
__device__ __half g_msgh[G_CNT * 64];
__device__ __half g_msgl[G_CNT * 64];
__device__ float  g_curf[N_UI * 64];
__device__ float  g_msgf[G_CNT * 64];
__device__ float  g_msgu[G_CNT * 64];
__device__ float  g_msgi[G_CNT * 64];
// cached fp16 conversions of the (layer-invariant) hyper matrices
__device__ __half g_uh16[(size_t)G_CNT * U_CNT];
__device__ __half g_ih16[(size_t)G_CNT * I_CNT];
__device__ __half g_fh16[(size_t)N_UI * G_CNT];
// [0]=cur absmax, [1]=cur binv, [2]=msg absmax, [3]=msg binv
__device__ float  g_scales[4];

// ---------------- PTX helpers ----------------
__device__ __forceinline__ uint32_t smem_u32(const void* p) {
    uint32_t a;
    asm("{ .reg .u64 t; cvta.to.shared.u64 t, %1; cvt.u32.u64 %0, t; }" : "=r"(a) : "l"(p));
    return a;
}
__device__ __forceinline__ uint32_t f16x2(float lo, float hi) {  // low=f16(lo), high=f16(hi)
    uint32_t r;
    asm("cvt.rn.f16x2.f32 %0, %1, %2;" : "=r"(r) : "f"(hi), "f"(lo));
    return r;
}
__device__ __forceinline__ void ldsm4(uint32_t* r, uint32_t addr) {
    asm volatile("ldmatrix.sync.aligned.m8n8.x4.shared.b16 {%0,%1,%2,%3}, [%4];"
                 : "=r"(r[0]), "=r"(r[1]), "=r"(r[2]), "=r"(r[3]) : "r"(addr));
}
__device__ __forceinline__ void ldsm4t(uint32_t* r, uint32_t addr) {
    asm volatile("ldmatrix.sync.aligned.m8n8.x4.trans.shared.b16 {%0,%1,%2,%3}, [%4];"
                 : "=r"(r[0]), "=r"(r[1]), "=r"(r[2]), "=r"(r[3]) : "r"(addr));
}
__device__ __forceinline__ void mma16816(float* c, const uint32_t* a, uint32_t b0, uint32_t b1) {
    asm volatile("mma.sync.aligned.m16n8k16.row.col.f32.f16.f16.f32 "
                 "{%0,%1,%2,%3}, {%4,%5,%6,%7}, {%8,%9}, {%0,%1,%2,%3};"
                 : "+f"(c[0]), "+f"(c[1]), "+f"(c[2]), "+f"(c[3])
                 : "r"(a[0]), "r"(a[1]), "r"(a[2]), "r"(a[3]), "r"(b0), "r"(b1));
}
__device__ __forceinline__ void cpasync16(uint32_t dst, const void* src, uint32_t sz) {
    asm volatile("cp.async.ca.shared.global [%0], [%1], 16, %2;"
                 :: "r"(dst), "l"(src), "r"(sz) : "memory");
}
__device__ __forceinline__ void cpasync_commit() {
    asm volatile("cp.async.commit_group;" ::: "memory");
}
__device__ __forceinline__ void cpasync_wait0() {
    asm volatile("cp.async.wait_group 0;" ::: "memory");
}
__device__ __forceinline__ void atomic_fmax(float* addr, float v) {   // v >= 0
    atomicMax((unsigned int*)addr, __float_as_uint(v));
}

// ---------------- smem layout: swizzled 128B rows ----------------
#define O_AH   0u        // A fp16 plane: 128 x 64 x 2B = 16K
#define O_BH   16384u    // B hi plane:    64 x 64 x 2B =  8K
#define O_BL   24576u    // B lo plane:                    8K
#define BUFB   32768u
#define SM_TOT 65536

// ---------------- fused GEMM:  C[M,64] = A[M,K] @ B[K,64] ----------------
// AF16=false: A fp32, inline convert to fp16 (values in [0,1)); optionally
//             stream converted tile to A16out (global [M][K] fp16 cache).
// AF16=true : A read from A16in via cp.async (no conversion, no staging).
// B = fp16 hi/lo planes (dynamically pre-scaled). C = binv*(A*Bh + A*Bl).
template <bool ATOMIC, bool AF16>
__global__ void __launch_bounds__(512)
gemm_mma(const float* __restrict__ A,
         const __half* __restrict__ A16in, __half* __restrict__ A16out,
         const __half* __restrict__ Bh_g, const __half* __restrict__ Bl_g,
         float* __restrict__ Cacc, float* __restrict__ outAdd,
         float* __restrict__ Cout, float* __restrict__ amax,
         const float* __restrict__ binv_p,
         int M, int K, int kChunk)
{
    extern __shared__ char sm[];
    const uint32_t sb = smem_u32(sm);
    const int tid  = threadIdx.x;
    const int lane = tid & 31;
    const int wid  = tid >> 5;
    const int wy   = wid & 3;        // m-quadrant (32 rows)
    const int wx   = wid >> 2;       // n-quadrant (16 cols)

    const int m0   = blockIdx.x << 7;
    const int k0   = blockIdx.y * kChunk;
    const int kEnd = min(k0 + kChunk, K);
    const int nb   = (kEnd - k0 + 63) >> 6;

    // fragment addressing (swizzled 16B units within 128B rows)
    const int li = lane >> 3, lr = lane & 7;
    const int chi = li >> 1, rsel = li & 1;
    const uint32_t ra0 = (uint32_t)((wy * 32 + rsel * 8 + lr) * 128);
    const uint32_t ra1 = ra0 + 16u * 128u;
    const uint32_t bconst = (uint32_t)((rsel * 8 + lr) * 128 + (((wx * 2 + chi) ^ lr) << 4));

    // A loader: row = tid>>2 (0..127), ac = tid&3
    const int ar = tid >> 2, ac = tid & 3;
    const float* Arow = A ? (A + (size_t)(m0 + ar) * K) : nullptr;
    const bool amok = (m0 + ar) < M;
    const uint32_t ar7 = (uint32_t)(ar & 7);

    // B loader (cp.async): kr = tid>>3 (0..63), bc16 = tid&7
    const int kr = tid >> 3, bc16 = tid & 7;
    const uint32_t bdst = (uint32_t)(kr * 128 + ((bc16 ^ (kr & 7)) << 4));

    float accA[2][2][4], accB[2][2][4];
#pragma unroll
    for (int i = 0; i < 2; i++)
#pragma unroll
        for (int j = 0; j < 2; j++)
#pragma unroll
            for (int q = 0; q < 4; q++) { accA[i][j][q] = 0.f; accB[i][j][q] = 0.f; }

    auto loadAreg = [&](int kb, float4* av) {
#pragma unroll
        for (int q = 0; q < 4; q++) {
            const int kk = (ac + 4 * q) * 4;
            float4 v = make_float4(0.f, 0.f, 0.f, 0.f);
            if (amok) {
                if (kb + kk + 3 < kEnd) v = *(const float4*)(Arow + kb + kk);
                else { float* pv = (float*)&v;
                    for (int t = 0; t < 4; t++) if (kb + kk + t < kEnd) pv[t] = Arow[kb + kk + t]; }
            }
            av[q] = v;
        }
    };
    auto storeA = [&](uint32_t bufo, int kb, const float4* av) {
#pragma unroll
        for (int q = 0; q < 4; q++) {
            const int k4 = ac + 4 * q;
            const float4 v = av[q];
            const uint32_t h01 = f16x2(v.x, v.y);
            const uint32_t h23 = f16x2(v.z, v.w);
            const uint32_t c16 = (uint32_t)(k4 >> 1);
            const uint32_t sub8 = (uint32_t)((k4 & 1) << 3);
            const uint32_t off = (uint32_t)(ar * 128) + ((c16 ^ ar7) << 4) + sub8;
            *(uint2*)(sm + bufo + O_AH + off) = make_uint2(h01, h23);
            if (A16out) {
                const int kk = k4 * 4;
                if (amok && kb + kk < kEnd)
                    *(uint2*)(A16out + (size_t)(m0 + ar) * K + kb + kk) = make_uint2(h01, h23);
            }
        }
    };
    auto issueA16 = [&](uint32_t bufo, int kb) {
#pragma unroll
        for (int w = 0; w < 2; w++) {
            const int c16 = ac + 4 * w;
            const uint32_t dst = (uint32_t)(ar * 128) + (((uint32_t)c16 ^ ar7) << 4);
            const uint32_t sz = (amok && kb + c16 * 8 < kEnd) ? 16u : 0u;
            cpasync16(sb + bufo + O_AH + dst,
                      A16in + (size_t)(m0 + ar) * K + kb + c16 * 8, sz);
        }
    };
    auto issueB = [&](uint32_t bufo, int kb) {
        const int kg = kb + kr;
        const uint32_t sz = (kg < kEnd) ? 16u : 0u;
        cpasync16(sb + bufo + O_BH + bdst, Bh_g + (size_t)kg * 64 + bc16 * 8, sz);
        cpasync16(sb + bufo + O_BL + bdst, Bl_g + (size_t)kg * 64 + bc16 * 8, sz);
    };

    // ---- fill buffer 0
    if (AF16) {
        issueA16(0u, k0);
        issueB(0u, k0);
        cpasync_commit();
        cpasync_wait0();
    } else {
        float4 av[4];
        loadAreg(k0, av);
        issueB(0u, k0);
        cpasync_commit();
        storeA(0u, k0, av);
        cpasync_wait0();
    }
    __syncthreads();

    for (int b = 0; b < nb; b++) {
        const uint32_t bo  = (uint32_t)(b & 1) * BUFB;
        const uint32_t nbo = BUFB - bo;
        const bool more = (b + 1 < nb);
        const int kbn = k0 + ((b + 1) << 6);

        float4 av[4];
        if (more) {
            if (AF16) issueA16(nbo, kbn);
            else      loadAreg(kbn, av);
            issueB(nbo, kbn);
            cpasync_commit();
        }

        // ---- MMA over this buffer (4 k-steps of 16)
#pragma unroll
        for (int ks = 0; ks < 4; ks++) {
            uint32_t ah[8], bh[4], bl[4];
            const uint32_t asw = (uint32_t)(((ks * 2 + chi) ^ lr) << 4);
            ldsm4(ah,     sb + bo + O_AH + ra0 + asw);
            ldsm4(ah + 4, sb + bo + O_AH + ra1 + asw);
            const uint32_t bad = sb + bo + bconst + (uint32_t)(ks * 2048);
            ldsm4t(bh, bad + O_BH);
            ldsm4t(bl, bad + O_BL);
#pragma unroll
            for (int mt = 0; mt < 2; mt++)
#pragma unroll
                for (int nt = 0; nt < 2; nt++)
                    mma16816(accA[mt][nt], ah + 4 * mt, bh[2 * nt], bh[2 * nt + 1]);
#pragma unroll
            for (int mt = 0; mt < 2; mt++)
#pragma unroll
                for (int nt = 0; nt < 2; nt++)
                    mma16816(accB[mt][nt], ah + 4 * mt, bl[2 * nt], bl[2 * nt + 1]);
        }

        if (more) {
            if (!AF16) storeA(nbo, kbn, av);
            cpasync_wait0();
        }
        __syncthreads();
    }

    // ---- epilogue
    const float binv = *binv_p;
    float vmax = 0.f;
#pragma unroll
    for (int mt = 0; mt < 2; mt++) {
        const int rbase = m0 + wy * 32 + mt * 16 + (lane >> 2);
#pragma unroll
        for (int nt = 0; nt < 2; nt++) {
            const int j = wx * 16 + nt * 8 + (lane & 3) * 2;
#pragma unroll
            for (int half = 0; half < 2; half++) {
                const int r = rbase + half * 8;
                if (r < M) {
                    const int idx = r * 64 + j;
                    const float v0 = (accA[mt][nt][half * 2]     + accB[mt][nt][half * 2])     * binv;
                    const float v1 = (accA[mt][nt][half * 2 + 1] + accB[mt][nt][half * 2 + 1]) * binv;
                    if (ATOMIC) {
                        atomicAdd(&Cacc[idx], v0);
                        atomicAdd(&Cacc[idx + 1], v1);
                    } else {
                        float2 o = *(float2*)&outAdd[idx];
                        o.x += v0; o.y += v1;
                        *(float2*)&outAdd[idx] = o;
                        Cout[idx]     = v0;
                        Cout[idx + 1] = v1;
                        vmax = fmaxf(vmax, fmaxf(fabsf(v0), fabsf(v1)));
                    }
                }
            }
        }
    }
    if (!ATOMIC) {
#pragma unroll
        for (int o = 16; o > 0; o >>= 1)
            vmax = fmaxf(vmax, __shfl_xor_sync(0xFFFFFFFFu, vmax, o));
        __shared__ float wm[16];
        if (lane == 0) wm[wid] = vmax;
        __syncthreads();
        if (tid == 0) {
            float m = wm[0];
#pragma unroll
            for (int i = 1; i < 16; i++) m = fmaxf(m, wm[i]);
            atomic_fmax(amax, m);
        }
    }
}

// ---------------- conversion: fp32 tensor -> scaled fp16 hi/lo planes ----------------
__global__ void conv_plane(const float* __restrict__ X,
                           __half* __restrict__ H, __half* __restrict__ L,
                           int n, const float* __restrict__ amax_p,
                           float* __restrict__ binv_p)
{
    const float m = fmaxf(*amax_p, 1e-30f);
    int e;
    frexpf(m, &e);                              // m = f * 2^e, f in [0.5,1)
    const float s = exp2f((float)(7 - e));      // scaled max in (64,128]
    if (blockIdx.x == 0 && threadIdx.x == 0) *binv_p = exp2f((float)(e - 7));
    const int stride = gridDim.x * blockDim.x;
    for (int i = blockIdx.x * blockDim.x + threadIdx.x; i < n; i += stride) {
        const float v = X[i] * s;
        const __half h = __float2half_rn(v);
        H[i] = h;
        L[i] = __float2half_rn(v - __half2float(h));
    }
}

// ---------------- init: out = [ue;ie;ge]; curf = concat(ue,ie); absmax ----------------
__global__ void init_all(const float* __restrict__ ue, const float* __restrict__ ie,
                         const float* __restrict__ ge, float* __restrict__ out,
                         float* __restrict__ curf, float* __restrict__ amax)
{
    const int i = blockIdx.x * blockDim.x + threadIdx.x;
    const int t = N_UI * 64;
    float v = 0.f;
    if (i < t) {
        v = (i < U_CNT * 64) ? ue[i] : ie[i - U_CNT * 64];
        out[i] = v;
        curf[i] = v;
    } else if (i < t + G_CNT * 64) {
        out[i] = ge[i - t];
    }
    float a = (i < t) ? fabsf(v) : 0.f;
#pragma unroll
    for (int o = 16; o > 0; o >>= 1)
        a = fmaxf(a, __shfl_xor_sync(0xFFFFFFFFu, a, o));
    __shared__ float wm[8];
    const int lane = threadIdx.x & 31, wid = threadIdx.x >> 5;
    if (lane == 0) wm[wid] = a;
    __syncthreads();
    if (threadIdx.x == 0) {
        float m = wm[0];
#pragma unroll
        for (int q = 1; q < 8; q++) m = fmaxf(m, wm[q]);
        atomic_fmax(amax, m);
    }
}

__global__ void zero_msgs(float* __restrict__ mu, float* __restrict__ mi,
                          float* __restrict__ scales)
{
    const int i = blockIdx.x * blockDim.x + threadIdx.x;
    if (i < G_CNT * 64) { mu[i] = 0.f; mi[i] = 0.f; }
    if (i == 0) { scales[0] = 0.f; scales[2] = 0.f; }
}

// ---------------- per-group attention + MLP fusion ----------------
__global__ void __launch_bounds__(256)
group_kernel(const float* __restrict__ mu, const float* __restrict__ mi,
             const float* __restrict__ gemb,
             const float* __restrict__ qc_w1, const float* __restrict__ qc_b1,
             const float* __restrict__ qc_w2,
             const float* __restrict__ user_w, const float* __restrict__ user_b,
             const float* __restrict__ item_w, const float* __restrict__ item_b,
             float* __restrict__ msgf, float* __restrict__ out,
             float* __restrict__ amax)
{
    const int sub = threadIdx.x >> 6, j = threadIdx.x & 63;
    const int g = blockIdx.x * 4 + sub;
    __shared__ float xu[4][64], xi[4][64], ge[4][64], du[4][64], di[4][64], rA[4][64], rB[4][64];

    xu[sub][j] = mu[g * 64 + j];
    xi[sub][j] = mi[g * 64 + j];
    ge[sub][j] = gemb[g * 64 + j];
    __syncthreads();
    {
        float hu = qc_b1[j], hi = qc_b1[j];
#pragma unroll 8
        for (int k = 0; k < 64; k++) {
            const float w = qc_w1[k * 64 + j];
            hu = fmaf(xu[sub][k], w, hu);
            hi = fmaf(xi[sub][k], w, hi);
        }
        const float w2 = qc_w2[j];
        rA[sub][j] = tanhf(hu) * w2;
        rB[sub][j] = tanhf(hi) * w2;
    }
    __syncthreads();
    for (int s = 32; s > 0; s >>= 1) {
        if (j < s) { rA[sub][j] += rA[sub][j + s]; rB[sub][j] += rB[sub][j + s]; }
        __syncthreads();
    }
    const float qu = rA[sub][0], qi = rB[sub][0];
    const float mx = fmaxf(qu, qi);
    const float eu = expf(qu - mx), ei = expf(qi - mx);
    const float w0 = eu / (eu + ei), w1 = ei / (eu + ei);
    const float c = w0 * xu[sub][j] + w1 * xi[sub][j];
    du[sub][j] = xu[sub][j] - c;
    di[sub][j] = xi[sub][j] - c;
    __syncthreads();

    float u2 = user_b[j], i2 = item_b[j];
#pragma unroll 8
    for (int k = 0; k < 64; k++) {
        u2 = fmaf(du[sub][k], user_w[k * 64 + j], u2);
        i2 = fmaf(di[sub][k], item_w[k * 64 + j], i2);
    }
#pragma unroll 8
    for (int k = 0; k < 64; k++) {
        const float gv = ge[sub][k];
        u2 = fmaf(gv, user_w[(64 + k) * 64 + j], u2);
        i2 = fmaf(gv, item_w[(64 + k) * 64 + j], i2);
    }
    const float m = u2 + i2 + c;
    out[N_UI * 64 + g * 64 + j] += m;
    msgf[g * 64 + j] = m;

    float a = fabsf(m);
#pragma unroll
    for (int o = 16; o > 0; o >>= 1)
        a = fmaxf(a, __shfl_xor_sync(0xFFFFFFFFu, a, o));
    __shared__ float wm[8];
    const int lane = threadIdx.x & 31, wid = threadIdx.x >> 5;
    if (lane == 0) wm[wid] = a;
    __syncthreads();
    if (threadIdx.x == 0) {
        float mm = wm[0];
#pragma unroll
        for (int q = 1; q < 8; q++) mm = fmaxf(mm, wm[q]);
        atomic_fmax(amax, mm);
    }
}

// ---------------- launch ----------------
extern "C" void kernel_launch(void* const* d_in, const int* in_sizes, int n_in,
                              void* d_out, int out_size)
{
    const float* user_emb   = (const float*)d_in[0];
    const float* item_emb   = (const float*)d_in[1];
    const float* group_emb  = (const float*)d_in[2];
    const float* user_hyper = (const float*)d_in[3];
    const float* item_hyper = (const float*)d_in[4];
    const float* full_hyper = (const float*)d_in[5];
    int wbase = 6;
    if (n_in >= 15 && in_sizes[6] == 1 && in_sizes[7] == 1) wbase = 8;
    const float* qc_w1  = (const float*)d_in[wbase + 0];
    const float* qc_b1  = (const float*)d_in[wbase + 1];
    const float* qc_w2  = (const float*)d_in[wbase + 2];
    const float* user_w = (const float*)d_in[wbase + 3];
    const float* user_b = (const float*)d_in[wbase + 4];
    const float* item_w = (const float*)d_in[wbase + 5];
    const float* item_b = (const float*)d_in[wbase + 6];
    float* out = (float*)d_out;

    __half *ch, *cl, *mh, *ml, *uh16, *ih16, *fh16;
    float *curf, *msgf, *mu, *mi, *scales;
    cudaGetSymbolAddress((void**)&ch, g_curh);
    cudaGetSymbolAddress((void**)&cl, g_curl);
    cudaGetSymbolAddress((void**)&mh, g_msgh);
    cudaGetSymbolAddress((void**)&ml, g_msgl);
    cudaGetSymbolAddress((void**)&curf, g_curf);
    cudaGetSymbolAddress((void**)&msgf, g_msgf);
    cudaGetSymbolAddress((void**)&mu, g_msgu);
    cudaGetSymbolAddress((void**)&mi, g_msgi);
    cudaGetSymbolAddress((void**)&uh16, g_uh16);
    cudaGetSymbolAddress((void**)&ih16, g_ih16);
    cudaGetSymbolAddress((void**)&fh16, g_fh16);
    cudaGetSymbolAddress((void**)&scales, g_scales);

    cudaFuncSetAttribute(gemm_mma<true,  false>, cudaFuncAttributeMaxDynamicSharedMemorySize, SM_TOT);
    cudaFuncSetAttribute(gemm_mma<true,  true>,  cudaFuncAttributeMaxDynamicSharedMemorySize, SM_TOT);
    cudaFuncSetAttribute(gemm_mma<false, false>, cudaFuncAttributeMaxDynamicSharedMemorySize, SM_TOT);
    cudaFuncSetAttribute(gemm_mma<false, true>,  cudaFuncAttributeMaxDynamicSharedMemorySize, SM_TOT);

    zero_msgs<<<(G_CNT * 64 + 255) / 256, 256>>>(mu, mi, scales);
    init_all<<<(N_TOT * 64 + 255) / 256, 256>>>(user_emb, item_emb, group_emb, out,
                                                curf, &scales[0]);
    conv_plane<<<4096, 256>>>(curf, ch, cl, N_UI * 64, &scales[0], &scales[1]);

    for (int l = 0; l < 2; l++) {
        zero_msgs<<<(G_CNT * 64 + 255) / 256, 256>>>(mu, mi, scales);

        if (l == 0) {
            // layer 0: fp32 A, convert inline, cache fp16 A for layer 1
            gemm_mma<true, false><<<dim3(16, 18), 512, SM_TOT>>>(
                user_hyper, nullptr, uh16, ch, cl, mu, nullptr, nullptr, nullptr,
                &scales[1], G_CNT, U_CNT, 1728);
            gemm_mma<true, false><<<dim3(16, 18), 512, SM_TOT>>>(
                item_hyper, nullptr, ih16,
                ch + (size_t)U_CNT * 64, cl + (size_t)U_CNT * 64,
                mi, nullptr, nullptr, nullptr,
                &scales[1], G_CNT, I_CNT, 3392);
        } else {
            // layer 1: cached fp16 A via cp.async
            gemm_mma<true, true><<<dim3(16, 18), 512, SM_TOT>>>(
                nullptr, uh16, nullptr, ch, cl, mu, nullptr, nullptr, nullptr,
                &scales[1], G_CNT, U_CNT, 1728);
            gemm_mma<true, true><<<dim3(16, 18), 512, SM_TOT>>>(
                nullptr, ih16, nullptr,
                ch + (size_t)U_CNT * 64, cl + (size_t)U_CNT * 64,
                mi, nullptr, nullptr, nullptr,
                &scales[1], G_CNT, I_CNT, 3392);
        }
        // attention + MLPs -> msg fp32 + absmax ; out_he += msg
        group_kernel<<<G_CNT / 4, 256>>>(mu, mi, group_emb,
            qc_w1 + l * 64 * 64, qc_b1 + l * 64, qc_w2 + l * 64,
            user_w + l * 128 * 64, user_b + l * 64,
            item_w + l * 128 * 64, item_b + l * 64, msgf, out, &scales[2]);
        // msg planes
        conv_plane<<<512, 256>>>(msgf, mh, ml, G_CNT * 64, &scales[2], &scales[3]);
        // node_emb = full_hyper @ msg ; out += ; cur fp32 + absmax
        if (l == 0) {
            gemm_mma<false, false><<<dim3(704, 1), 512, SM_TOT>>>(
                full_hyper, nullptr, fh16, mh, ml, nullptr, out, curf, &scales[0],
                &scales[3], N_UI, G_CNT, 2048);
            conv_plane<<<4096, 256>>>(curf, ch, cl, N_UI * 64, &scales[0], &scales[1]);
        } else {
            gemm_mma<false, true><<<dim3(704, 1), 512, SM_TOT>>>(
                nullptr, fh16, nullptr, mh, ml, nullptr, out, curf, &scales[0],
                &scales[3], N_UI, G_CNT, 2048);
        }
    }
    (void)in_sizes; (void)n_in; (void)out_size;
}